// round 5
// baseline (speedup 1.0000x reference)
#include <cuda_runtime.h>
#include <math.h>
#include <stdint.h>

#define K_COMP 8192
#define N_SAMP 8192
#define B_X    2048
#define D_W    13

#define LOG_2PI 1.8378770664093453f
#define L2E     1.4426950408889634f

#define MT 128                     // M rows per block tile (16 ty x 8 rows)
#define NT 256                     // N cols per tile       (16 tx x 16 cols)
#define NCHUNK 16                  // n-chunks (blockIdx.y)
#define TPC ((K_COMP / NT) / NCHUNK)  // 2 n-tiles per block
#define MTILES (N_SAMP / MT)       // 64

typedef unsigned long long ull;

// ---------------- scratch (no allocations allowed) ----------------
__device__ float g_empT[D_W][K_COMP];   // emp transposed [d][k]
__device__ float g_wT[D_W][N_SAMP];     // w transposed  [d][s]
__device__ float g_u[K_COMP];           // L2E*(c_k - 0.5*inv_var*en_k)
__device__ float g_g[K_COMP];           // L2E*inv_var
__device__ float g_wn[N_SAMP];          // ||w_s||^2
__device__ float g_dsum[N_SAMP];        // sum_b (y_pred - y)^2
__device__ float g_SP[NCHUNK][N_SAMP];  // per-chunk partial exp-sums
__device__ float g_q[N_SAMP];           // log(sum)

__device__ __forceinline__ float tanh_fast(float x) {
    float r; asm("tanh.approx.f32 %0, %1;" : "=f"(r) : "f"(x)); return r;
}
__device__ __forceinline__ float exp2_fast(float x) {
    float r; asm("ex2.approx.f32 %0, %1;" : "=f"(r) : "f"(x)); return r;
}
__device__ __forceinline__ ull pack2(float lo, float hi) {
    ull r; asm("mov.b64 %0, {%1, %2};" : "=l"(r) : "f"(lo), "f"(hi)); return r;
}
__device__ __forceinline__ void unpack2(ull v, float& lo, float& hi) {
    asm("mov.b64 {%0, %1}, %2;" : "=f"(lo), "=f"(hi) : "l"(v));
}
__device__ __forceinline__ ull fma2(ull a, ull b, ull c) {
    ull d; asm("fma.rn.f32x2 %0, %1, %2, %3;" : "=l"(d) : "l"(a), "l"(b), "l"(c)); return d;
}

// ---------------- kernel 1: per-component precompute ----------------
__global__ void prep_k(const float* __restrict__ emp, const float* __restrict__ rhos) {
    int k = blockIdx.x * blockDim.x + threadIdx.x;
    if (k >= K_COMP) return;
    float rho = rhos[k];
    float sd = (rho > 20.f) ? rho : log1pf(__expf(rho));   // softplus
    float var = sd * sd;
    float inv = 1.f / var;
    float en = 0.f;
#pragma unroll
    for (int d = 0; d < D_W; d++) {
        float v = __ldg(&emp[k * D_W + d]);
        g_empT[d][k] = v;
        en = fmaf(v, v, en);
    }
    float c = -0.5f * ((float)D_W * LOG_2PI + (float)D_W * logf(var));
    g_u[k] = L2E * (c - 0.5f * inv * en);
    g_g[k] = L2E * inv;
}

// ---------------- kernel 2: fused per-sample prep + regression ----------------
// one warp per sample: builds w (lanes 0..12), writes g_wT/g_wn, then the
// 2-2-1 MLP over 2048 x points. MUFU(tanh)-bound.
__global__ __launch_bounds__(1024) void reg_kernel(const float* __restrict__ x,
                                                   const float* __restrict__ y,
                                                   const float* __restrict__ emp,
                                                   const float* __restrict__ eps,
                                                   const float* __restrict__ rhos,
                                                   const int* __restrict__ idxs) {
    __shared__ float sx[B_X];
    __shared__ float sy[B_X];
    for (int i = threadIdx.x; i < B_X; i += blockDim.x) { sx[i] = x[i]; sy[i] = y[i]; }
    __syncthreads();

    int warp = threadIdx.x >> 5, lane = threadIdx.x & 31;
    int s = blockIdx.x * (blockDim.x >> 5) + warp;

    int idx = __shfl_sync(0xffffffffu, idxs[s], 0);
    float rho = rhos[idx];
    float sd = (rho > 20.f) ? rho : log1pf(__expf(rho));

    float wd = 0.f;
    if (lane < D_W)
        wd = fmaf(eps[s * D_W + lane], sd, emp[idx * D_W + lane]);
    // ||w||^2 across lanes
    float wn = wd * wd;
#pragma unroll
    for (int o = 16; o; o >>= 1) wn += __shfl_xor_sync(0xffffffffu, wn, o);
    if (lane < D_W) g_wT[lane][s] = wd;
    if (lane == 0)  g_wn[s] = wn;

    float p[D_W];
#pragma unroll
    for (int d = 0; d < D_W; d++) p[d] = __shfl_sync(0xffffffffu, wd, d);
    float w10 = p[0], w11 = p[1], b10 = p[2], b11 = p[3];
    float w200 = p[4], w201 = p[5], w210 = p[6], w211 = p[7];
    float b20 = p[8], b21 = p[9], w30 = p[10], w31 = p[11], b3 = p[12];

    float acc = 0.f;
#pragma unroll 4
    for (int t = 0; t < B_X / 32; t++) {
        int pix = t * 32 + lane;
        float xv = sx[pix], yv = sy[pix];
        float h0 = tanh_fast(fmaf(w10, xv, b10));
        float h1 = tanh_fast(fmaf(w11, xv, b11));
        float z0 = tanh_fast(fmaf(w200, h0, fmaf(w201, h1, b20)));
        float z1 = tanh_fast(fmaf(w210, h0, fmaf(w211, h1, b21)));
        float yp = fmaf(w30, z0, fmaf(w31, z1, b3));
        float d = yp - yv;
        acc = fmaf(d, d, acc);
    }
#pragma unroll
    for (int o = 16; o; o >>= 1) acc += __shfl_xor_sync(0xffffffffu, acc, o);
    if (lane == 0) g_dsum[s] = acc;
}

// ---------------- kernel 3: GEMM + unshifted exp-sum ----------------
// 256 thr = 16tx x 16ty; per-thread 8M x 16N (64 f32x2 accumulators).
// Both N-tiles staged into double-buffered smem up front -> ONE sync total;
// warps drift freely so epilogue MUFU overlaps other warps' FMA mainloop.
__global__ __launch_bounds__(256, 1) void lse_kernel() {
    __shared__ __align__(16) ull sw2[D_W][MT];            // (w,w) dup pairs
    __shared__ __align__(16) ull se2[TPC][D_W][NT / 2];   // (e0,e1) pairs
    __shared__ __align__(16) ull su2[TPC][NT / 2];
    __shared__ __align__(16) ull sg2[TPC][NT / 2];

    int tid = threadIdx.x;
    int tx = tid & 15;        // N direction: 8 col-pairs = 16 cols
    int ty = tid >> 4;        // M direction: 8 rows
    int m0 = blockIdx.x * MT;

    // stage w tile (dup pairs)
    for (int i = tid; i < D_W * MT; i += 256) {
        int d = i >> 7, r = i & (MT - 1);
        float v = g_wT[d][m0 + r];
        sw2[d][r] = pack2(v, v);
    }
    // stage BOTH n-tiles (e pairs + u + g)
#pragma unroll
    for (int t = 0; t < TPC; t++) {
        int n0 = (blockIdx.y * TPC + t) * NT;
        for (int i = tid; i < D_W * (NT / 2) + NT; i += 256) {
            if (i < D_W * (NT / 2)) {
                int d = i >> 7, c = i & 127;
                float2 e = *(const float2*)&g_empT[d][n0 + 2 * c];
                se2[t][d][c] = pack2(e.x, e.y);
            } else if (i < D_W * (NT / 2) + NT / 2) {
                int c = i - D_W * (NT / 2);
                float2 u = *(const float2*)&g_u[n0 + 2 * c];
                su2[t][c] = pack2(u.x, u.y);
            } else {
                int c = i - D_W * (NT / 2) - NT / 2;
                float2 g = *(const float2*)&g_g[n0 + 2 * c];
                sg2[t][c] = pack2(g.x, g.y);
            }
        }
    }
    float wnh[8], S[8];
#pragma unroll
    for (int r = 0; r < 8; r++) {
        wnh[r] = -0.5f * g_wn[m0 + ty * 8 + r];
        S[r] = 0.f;
    }
    __syncthreads();    // the ONLY block-wide sync

#pragma unroll
    for (int t = 0; t < TPC; t++) {
        ull acc[8][8];   // [row][colpair]; init A = -0.5||w||^2
#pragma unroll
        for (int r = 0; r < 8; r++) {
            ull iv = pack2(wnh[r], wnh[r]);
#pragma unroll
            for (int c = 0; c < 8; c++) acc[r][c] = iv;
        }

#pragma unroll
        for (int k = 0; k < D_W; k++) {
            ulonglong2 w01 = *(const ulonglong2*)&sw2[k][ty * 8 + 0];
            ulonglong2 w23 = *(const ulonglong2*)&sw2[k][ty * 8 + 2];
            ulonglong2 w45 = *(const ulonglong2*)&sw2[k][ty * 8 + 4];
            ulonglong2 w67 = *(const ulonglong2*)&sw2[k][ty * 8 + 6];
            ulonglong2 e01 = *(const ulonglong2*)&se2[t][k][tx * 8 + 0];
            ulonglong2 e23 = *(const ulonglong2*)&se2[t][k][tx * 8 + 2];
            ulonglong2 e45 = *(const ulonglong2*)&se2[t][k][tx * 8 + 4];
            ulonglong2 e67 = *(const ulonglong2*)&se2[t][k][tx * 8 + 6];
            ull wr[8] = { w01.x, w01.y, w23.x, w23.y, w45.x, w45.y, w67.x, w67.y };
            ull ec[8] = { e01.x, e01.y, e23.x, e23.y, e45.x, e45.y, e67.x, e67.y };
#pragma unroll
            for (int r = 0; r < 8; r++)
#pragma unroll
                for (int c = 0; c < 8; c++)
                    acc[r][c] = fma2(wr[r], ec[c], acc[r][c]);
        }

        // epilogue: t2 = g_k*A + u_k  (base-2, unshifted: arg < 0 always; far
        // components underflow to 0 harmlessly, own component keeps S > 2^-50)
        {
            ulonglong2 g01 = *(const ulonglong2*)&sg2[t][tx * 8 + 0];
            ulonglong2 g23 = *(const ulonglong2*)&sg2[t][tx * 8 + 2];
            ulonglong2 g45 = *(const ulonglong2*)&sg2[t][tx * 8 + 4];
            ulonglong2 g67 = *(const ulonglong2*)&sg2[t][tx * 8 + 6];
            ulonglong2 u01 = *(const ulonglong2*)&su2[t][tx * 8 + 0];
            ulonglong2 u23 = *(const ulonglong2*)&su2[t][tx * 8 + 2];
            ulonglong2 u45 = *(const ulonglong2*)&su2[t][tx * 8 + 4];
            ulonglong2 u67 = *(const ulonglong2*)&su2[t][tx * 8 + 6];
            ull g2[8] = { g01.x, g01.y, g23.x, g23.y, g45.x, g45.y, g67.x, g67.y };
            ull u2[8] = { u01.x, u01.y, u23.x, u23.y, u45.x, u45.y, u67.x, u67.y };
#pragma unroll
            for (int c = 0; c < 8; c++) {
#pragma unroll
                for (int r = 0; r < 8; r++) {
                    ull t2 = fma2(g2[c], acc[r][c], u2[c]);
                    float t0, t1;
                    unpack2(t2, t0, t1);
                    S[r] += exp2_fast(t0) + exp2_fast(t1);
                }
            }
        }
    }

    // reduce across the 16 tx lanes (xor over lane bits 0-3)
#pragma unroll
    for (int r = 0; r < 8; r++) {
        float v = S[r];
#pragma unroll
        for (int o = 8; o; o >>= 1) v += __shfl_xor_sync(0xffffffffu, v, o);
        if (tx == 0) g_SP[blockIdx.y][m0 + ty * 8 + r] = v;
    }
}

// ---------------- kernel 4: parallel per-sample reduction + log ----------------
__global__ void reduce_sp() {
    int s = blockIdx.x * blockDim.x + threadIdx.x;
    if (s >= N_SAMP) return;
    float S = 0.f;
#pragma unroll
    for (int c = 0; c < NCHUNK; c++) S += g_SP[c][s];
    g_q[s] = logf(S);
}

// ---------------- kernel 5: final deterministic reduction ----------------
__global__ __launch_bounds__(1024) void final_kernel(float* __restrict__ out) {
    __shared__ double sh[3][32];
    int tid = threadIdx.x;
    double qs = 0.0, wns = 0.0, ds = 0.0;
    for (int s = tid; s < N_SAMP; s += 1024) {
        qs  += (double)g_q[s];
        wns += (double)g_wn[s];
        ds  += (double)g_dsum[s];
    }
    int lane = tid & 31, warp = tid >> 5;
#pragma unroll
    for (int o = 16; o; o >>= 1) {
        qs  += __shfl_xor_sync(0xffffffffu, qs, o);
        wns += __shfl_xor_sync(0xffffffffu, wns, o);
        ds  += __shfl_xor_sync(0xffffffffu, ds, o);
    }
    if (lane == 0) { sh[0][warp] = qs; sh[1][warp] = wns; sh[2][warp] = ds; }
    __syncthreads();
    if (warp == 0) {
        qs = sh[0][lane]; wns = sh[1][lane]; ds = sh[2][lane];
#pragma unroll
        for (int o = 16; o; o >>= 1) {
            qs  += __shfl_xor_sync(0xffffffffu, qs, o);
            wns += __shfl_xor_sync(0xffffffffu, wns, o);
            ds  += __shfl_xor_sync(0xffffffffu, ds, o);
        }
        if (lane == 0) {
            const double LOG_2PI_D = 1.837877066409345483560659472811;
            double mean_q  = qs / (double)N_SAMP - log((double)K_COMP);
            double mean_wn = wns / (double)N_SAMP;
            double mean_d  = ds / (double)N_SAMP;
            double data_lp = -0.5 * 5.0 * mean_d
                           + (double)B_X * 0.5 * (log(5.0) - LOG_2PI_D);
            double prior   = -0.5 * mean_wn - 0.5 * (double)D_W * LOG_2PI_D;
            double kl      = mean_q - prior;
            out[0] = (float)(data_lp - kl);
        }
    }
}

// ---------------- launch ----------------
extern "C" void kernel_launch(void* const* d_in, const int* in_sizes, int n_in,
                              void* d_out, int out_size) {
    const float* emp  = (const float*)d_in[0];
    const float* rhos = (const float*)d_in[1];
    const float* x    = (const float*)d_in[2];
    const float* y    = (const float*)d_in[3];
    const float* eps  = (const float*)d_in[4];
    const int*   idxs = (const int*)d_in[5];
    float* out = (float*)d_out;

    prep_k<<<(K_COMP + 255) / 256, 256>>>(emp, rhos);
    reg_kernel<<<N_SAMP / 32, 1024>>>(x, y, emp, eps, rhos, idxs);
    lse_kernel<<<dim3(MTILES, NCHUNK), 256>>>();
    reduce_sp<<<N_SAMP / 256, 256>>>();
    final_kernel<<<1, 1024>>>(out);
}

// round 6
// speedup vs baseline: 1.9311x; 1.9311x over previous
#include <cuda_runtime.h>
#include <math.h>
#include <stdint.h>

#define K_COMP 8192
#define N_SAMP 8192
#define B_X    2048
#define D_W    13

#define LOG_2PI 1.8378770664093453f
#define L2E     1.4426950408889634f

#define NRB   (N_SAMP / 16)     // 512 row-blocks of 16 samples
#define NNB   (K_COMP / 8)      // 1024 col-blocks of 8 components
#define NC    8                 // n-chunks
#define NB_PC (NNB / NC)        // 128 col-blocks per chunk

// ---------------- scratch (no allocations allowed) ----------------
__device__ float  g_w16[N_SAMP * 16];     // fp32 w, padded k=13..15 = 0
__device__ float  g_wn[N_SAMP];           // ||w||^2 (fp32 exact)
__device__ float4 g_gu[K_COMP / 2];       // (g0,g1,u0,u1) per col-pair
__device__ uint4  g_Afrag[NRB * 32];      // per-lane A fragments (bf16x2 x4)
__device__ uint2  g_Bfrag[NNB * 32];      // per-lane B fragments (bf16x2 x2)
__device__ float  g_dsum[N_SAMP];         // sum_b (y_pred - y)^2
__device__ float  g_SP[NC][N_SAMP];       // per-chunk partial exp-sums

__device__ __forceinline__ float tanh_fast(float x) {
    float r; asm("tanh.approx.f32 %0, %1;" : "=f"(r) : "f"(x)); return r;
}
__device__ __forceinline__ float exp2_fast(float x) {
    float r; asm("ex2.approx.f32 %0, %1;" : "=f"(r) : "f"(x)); return r;
}
// pack two f32 -> bf16x2, lo in low 16 bits
__device__ __forceinline__ unsigned packbf(float lo, float hi) {
    unsigned r; asm("cvt.rn.bf16x2.f32 %0, %1, %2;" : "=r"(r) : "f"(hi), "f"(lo)); return r;
}

// ---------------- kernel 1: per-component g,u ----------------
__global__ void prep_k(const float* __restrict__ emp, const float* __restrict__ rhos) {
    int k = blockIdx.x * blockDim.x + threadIdx.x;
    if (k >= K_COMP) return;
    float rho = rhos[k];
    float sd = (rho > 20.f) ? rho : log1pf(__expf(rho));   // softplus
    float var = sd * sd;
    float inv = 1.f / var;
    float en = 0.f;
#pragma unroll
    for (int d = 0; d < D_W; d++) {
        float v = __ldg(&emp[k * D_W + d]);
        en = fmaf(v, v, en);
    }
    float c = -0.5f * ((float)D_W * LOG_2PI + (float)D_W * logf(var));
    float g = L2E * inv;
    float u = L2E * (c - 0.5f * inv * en);
    // write into the float4 pair table (two threads fill disjoint halves)
    float* gu = (float*)&g_gu[k >> 1];
    gu[(k & 1) + 0] = g;   // .x / .y
    gu[(k & 1) + 2] = u;   // .z / .w
}

// ---------------- kernel 2: per-sample w (padded), norms ----------------
__global__ void prep_s(const float* __restrict__ emp, const float* __restrict__ eps,
                       const float* __restrict__ rhos, const int* __restrict__ idxs) {
    int s = blockIdx.x * blockDim.x + threadIdx.x;
    if (s >= N_SAMP) return;
    int idx = idxs[s];
    float rho = rhos[idx];
    float sd = (rho > 20.f) ? rho : log1pf(__expf(rho));
    float wn = 0.f;
#pragma unroll
    for (int d = 0; d < 16; d++) {
        float w = 0.f;
        if (d < D_W) w = fmaf(__ldg(&eps[s * D_W + d]), sd, __ldg(&emp[idx * D_W + d]));
        g_w16[s * 16 + d] = w;
        wn = fmaf(w, w, wn);
    }
    g_wn[s] = wn;
}

// ---------------- kernel 3: build mma fragments (per-lane layout) ----------------
// m16n8k16 row.col: gid = lane>>2, tg = lane&3
// A: reg0=(r=gid,k=2tg,2tg+1) reg1=(r=gid+8,same) reg2=(r=gid,k+8) reg3=(r=gid+8,k+8)
// B: reg0=(n=gid,k=2tg,2tg+1) reg1=(n=gid,k=2tg+8,2tg+9)
__global__ void prep_frag(const float* __restrict__ emp) {
    int tid = blockIdx.x * blockDim.x + threadIdx.x;
    if (tid < NRB * 32) {
        int lane = tid & 31, gid = lane >> 2, tg = lane & 3;
        int rb = tid >> 5;
        const float* w0 = &g_w16[(rb * 16 + gid) * 16];
        const float* w8 = &g_w16[(rb * 16 + gid + 8) * 16];
        int k0 = tg * 2;
        uint4 r;
        r.x = packbf(w0[k0], w0[k0 + 1]);
        r.y = packbf(w8[k0], w8[k0 + 1]);
        r.z = packbf(w0[k0 + 8], w0[k0 + 9]);
        r.w = packbf(w8[k0 + 8], w8[k0 + 9]);
        g_Afrag[tid] = r;
    } else {
        int t2 = tid - NRB * 32;           // < NNB*32 by grid sizing
        int lane = t2 & 31, gid = lane >> 2, tg = lane & 3;
        int nb = t2 >> 5;
        int n = nb * 8 + gid;
        int k0 = tg * 2;
        float e0 = __ldg(&emp[n * D_W + k0]);
        float e1 = __ldg(&emp[n * D_W + k0 + 1]);
        float e2 = (k0 + 8 < D_W) ? __ldg(&emp[n * D_W + k0 + 8]) : 0.f;
        float e3 = (k0 + 9 < D_W) ? __ldg(&emp[n * D_W + k0 + 9]) : 0.f;
        uint2 r;
        r.x = packbf(e0, e1);
        r.y = packbf(e2, e3);
        g_Bfrag[t2] = r;
    }
}

// ---------------- kernel 4: regression data term ----------------
__global__ __launch_bounds__(1024) void reg_kernel(const float* __restrict__ x,
                                                   const float* __restrict__ y) {
    __shared__ float sx[B_X];
    __shared__ float sy[B_X];
    for (int i = threadIdx.x; i < B_X; i += blockDim.x) { sx[i] = x[i]; sy[i] = y[i]; }
    __syncthreads();

    int warp = threadIdx.x >> 5, lane = threadIdx.x & 31;
    int s = blockIdx.x * (blockDim.x >> 5) + warp;

    float wd = (lane < D_W) ? g_w16[s * 16 + lane] : 0.f;
    float p[D_W];
#pragma unroll
    for (int d = 0; d < D_W; d++) p[d] = __shfl_sync(0xffffffffu, wd, d);
    float w10 = p[0], w11 = p[1], b10 = p[2], b11 = p[3];
    float w200 = p[4], w201 = p[5], w210 = p[6], w211 = p[7];
    float b20 = p[8], b21 = p[9], w30 = p[10], w31 = p[11], b3 = p[12];

    float acc = 0.f;
#pragma unroll 4
    for (int t = 0; t < B_X / 32; t++) {
        int pix = t * 32 + lane;
        float xv = sx[pix], yv = sy[pix];
        float h0 = tanh_fast(fmaf(w10, xv, b10));
        float h1 = tanh_fast(fmaf(w11, xv, b11));
        float z0 = tanh_fast(fmaf(w200, h0, fmaf(w201, h1, b20)));
        float z1 = tanh_fast(fmaf(w210, h0, fmaf(w211, h1, b21)));
        float yp = fmaf(w30, z0, fmaf(w31, z1, b3));
        float d = yp - yv;
        acc = fmaf(d, d, acc);
    }
#pragma unroll
    for (int o = 16; o; o >>= 1) acc += __shfl_xor_sync(0xffffffffu, acc, o);
    if (lane == 0) g_dsum[s] = acc;
}

// ---------------- kernel 5: tensor-core GEMM + exp2 sum ----------------
// grid 512 = NC(8) chunks x 64 groups; 8 warps/block, one 16-row block/warp.
// No shared memory; frags + (g,u) streamed via LDG; MUFU(ex2)-bound.
__global__ __launch_bounds__(256) void lse_mma() {
    int wid = threadIdx.x >> 5, lane = threadIdx.x & 31;
    int gid = lane >> 2, tg = lane & 3;
    int chunk = blockIdx.x >> 6;          // 0..7
    int grp   = blockIdx.x & 63;
    int rb = grp * 8 + wid;               // 0..511
    int s0 = rb * 16;

    uint4 af = g_Afrag[rb * 32 + lane];
    float hw0 = -0.5f * g_wn[s0 + gid];
    float hw8 = -0.5f * g_wn[s0 + gid + 8];
    float S0 = 0.f, S8 = 0.f;

    int nb0 = chunk * NB_PC;
#pragma unroll 4
    for (int i = 0; i < NB_PC; i++) {
        int nb = nb0 + i;
        uint2 bf = g_Bfrag[nb * 32 + lane];
        float4 gu = g_gu[nb * 4 + tg];
        float c0 = hw0, c1 = hw0, c2 = hw8, c3 = hw8;
        asm volatile(
            "mma.sync.aligned.m16n8k16.row.col.f32.bf16.bf16.f32 "
            "{%0,%1,%2,%3}, {%4,%5,%6,%7}, {%8,%9}, {%0,%1,%2,%3};"
            : "+f"(c0), "+f"(c1), "+f"(c2), "+f"(c3)
            : "r"(af.x), "r"(af.y), "r"(af.z), "r"(af.w),
              "r"(bf.x), "r"(bf.y));
        // t = g*(dot - 0.5||w||^2) + u  (base-2, unshifted; always < 0)
        S0 += exp2_fast(fmaf(gu.x, c0, gu.z));
        S0 += exp2_fast(fmaf(gu.y, c1, gu.w));
        S8 += exp2_fast(fmaf(gu.x, c2, gu.z));
        S8 += exp2_fast(fmaf(gu.y, c3, gu.w));
    }

    // combine the 4 lanes of each group (they cover disjoint col sets)
    S0 += __shfl_xor_sync(0xffffffffu, S0, 1);
    S0 += __shfl_xor_sync(0xffffffffu, S0, 2);
    S8 += __shfl_xor_sync(0xffffffffu, S8, 1);
    S8 += __shfl_xor_sync(0xffffffffu, S8, 2);
    if (tg == 0) {
        g_SP[chunk][s0 + gid]     = S0;
        g_SP[chunk][s0 + gid + 8] = S8;
    }
}

// ---------------- kernel 6: final deterministic reduction ----------------
__global__ __launch_bounds__(1024) void final_kernel(float* __restrict__ out) {
    __shared__ double sh[3][32];
    int tid = threadIdx.x;
    double qs = 0.0, wns = 0.0, ds = 0.0;
    for (int s = tid; s < N_SAMP; s += 1024) {
        float S = 0.f;
#pragma unroll
        for (int c = 0; c < NC; c++) S += g_SP[c][s];
        qs  += (double)logf(S);
        wns += (double)g_wn[s];
        ds  += (double)g_dsum[s];
    }
    int lane = tid & 31, warp = tid >> 5;
#pragma unroll
    for (int o = 16; o; o >>= 1) {
        qs  += __shfl_xor_sync(0xffffffffu, qs, o);
        wns += __shfl_xor_sync(0xffffffffu, wns, o);
        ds  += __shfl_xor_sync(0xffffffffu, ds, o);
    }
    if (lane == 0) { sh[0][warp] = qs; sh[1][warp] = wns; sh[2][warp] = ds; }
    __syncthreads();
    if (warp == 0) {
        qs = sh[0][lane]; wns = sh[1][lane]; ds = sh[2][lane];
#pragma unroll
        for (int o = 16; o; o >>= 1) {
            qs  += __shfl_xor_sync(0xffffffffu, qs, o);
            wns += __shfl_xor_sync(0xffffffffu, wns, o);
            ds  += __shfl_xor_sync(0xffffffffu, ds, o);
        }
        if (lane == 0) {
            const double LOG_2PI_D = 1.837877066409345483560659472811;
            double mean_q  = qs / (double)N_SAMP - log((double)K_COMP);
            double mean_wn = wns / (double)N_SAMP;
            double mean_d  = ds / (double)N_SAMP;
            double data_lp = -0.5 * 5.0 * mean_d
                           + (double)B_X * 0.5 * (log(5.0) - LOG_2PI_D);
            double prior   = -0.5 * mean_wn - 0.5 * (double)D_W * LOG_2PI_D;
            double kl      = mean_q - prior;
            out[0] = (float)(data_lp - kl);
        }
    }
}

// ---------------- launch ----------------
extern "C" void kernel_launch(void* const* d_in, const int* in_sizes, int n_in,
                              void* d_out, int out_size) {
    const float* emp  = (const float*)d_in[0];
    const float* rhos = (const float*)d_in[1];
    const float* x    = (const float*)d_in[2];
    const float* y    = (const float*)d_in[3];
    const float* eps  = (const float*)d_in[4];
    const int*   idxs = (const int*)d_in[5];
    float* out = (float*)d_out;

    prep_k<<<(K_COMP + 255) / 256, 256>>>(emp, rhos);
    prep_s<<<(N_SAMP + 255) / 256, 256>>>(emp, eps, rhos, idxs);
    prep_frag<<<(NRB * 32 + NNB * 32) / 256, 256>>>(emp);
    reg_kernel<<<N_SAMP / 32, 1024>>>(x, y);
    lse_mma<<<NC * 64, 256>>>();
    final_kernel<<<1, 1024>>>(out);
}

// round 7
// speedup vs baseline: 2.8219x; 1.4613x over previous
#include <cuda_runtime.h>
#include <math.h>
#include <stdint.h>

#define K_COMP 8192
#define N_SAMP 8192
#define B_X    2048
#define D_W    13

#define LOG_2PI 1.8378770664093453f
#define L2E     1.4426950408889634f

#define NRB   (N_SAMP / 16)     // 512 row-blocks of 16 samples
#define NNB   (K_COMP / 8)      // 1024 col-blocks of 8 components
#define NC    8                 // n-chunks
#define NB_PC (NNB / NC)        // 128 col-blocks per chunk

#define REG_BLOCKS (N_SAMP / 8)         // 1024 (8 warps/block, 1 sample/warp)
#define LSE_BLOCKS (NC * 64)            // 512
#define RED_BLOCKS 32

// ---------------- scratch (no allocations allowed) ----------------
__device__ float  g_w16[N_SAMP * 16];     // fp32 w, padded k=13..15 = 0
__device__ float  g_wn[N_SAMP];           // ||w||^2 (fp32 exact)
__device__ float4 g_gu[K_COMP / 2];       // (g0,g1,u0,u1) per col-pair
__device__ uint4  g_Afrag[NRB * 32];      // per-lane A fragments (bf16x2 x4)
__device__ uint2  g_Bfrag[NNB * 32];      // per-lane B fragments (bf16x2 x2)
__device__ float  g_dsum[N_SAMP];         // sum_b (y_pred - y)^2
__device__ float  g_SP[NC][N_SAMP];       // per-chunk partial exp-sums
__device__ double g_part[RED_BLOCKS][3];  // per-block (q, wn, dsum) sums

__device__ __forceinline__ float tanh_fast(float x) {
    float r; asm("tanh.approx.f32 %0, %1;" : "=f"(r) : "f"(x)); return r;
}
__device__ __forceinline__ float exp2_fast(float x) {
    float r; asm("ex2.approx.f32 %0, %1;" : "=f"(r) : "f"(x)); return r;
}
// pack two f32 -> bf16x2, lo in low 16 bits
__device__ __forceinline__ unsigned packbf(float lo, float hi) {
    unsigned r; asm("cvt.rn.bf16x2.f32 %0, %1, %2;" : "=r"(r) : "f"(hi), "f"(lo)); return r;
}

// ---------------- kernel 1: per-component g,u + B fragments ----------------
__global__ void prep_comp(const float* __restrict__ emp, const float* __restrict__ rhos) {
    int tid = blockIdx.x * blockDim.x + threadIdx.x;
    if (tid < K_COMP) {
        int k = tid;
        float rho = rhos[k];
        float sd = (rho > 20.f) ? rho : log1pf(__expf(rho));   // softplus
        float var = sd * sd;
        float inv = 1.f / var;
        float en = 0.f;
#pragma unroll
        for (int d = 0; d < D_W; d++) {
            float v = __ldg(&emp[k * D_W + d]);
            en = fmaf(v, v, en);
        }
        float c = -0.5f * ((float)D_W * LOG_2PI + (float)D_W * logf(var));
        float g = L2E * inv;
        float u = L2E * (c - 0.5f * inv * en);
        float* gu = (float*)&g_gu[k >> 1];
        gu[(k & 1) + 0] = g;
        gu[(k & 1) + 2] = u;
    } else {
        // B fragments: m16n8k16 row.col B layout (n=gid, k=2tg.. / +8)
        int t2 = tid - K_COMP;             // < NNB*32
        int lane = t2 & 31, gid = lane >> 2, tg = lane & 3;
        int nb = t2 >> 5;
        int n = nb * 8 + gid;
        int k0 = tg * 2;
        float e0 = __ldg(&emp[n * D_W + k0]);
        float e1 = __ldg(&emp[n * D_W + k0 + 1]);
        float e2 = (k0 + 8 < D_W) ? __ldg(&emp[n * D_W + k0 + 8]) : 0.f;
        float e3 = (k0 + 9 < D_W) ? __ldg(&emp[n * D_W + k0 + 9]) : 0.f;
        uint2 r;
        r.x = packbf(e0, e1);
        r.y = packbf(e2, e3);
        g_Bfrag[t2] = r;
    }
}

// ---------------- kernel 2: per-sample w, norms, A fragments ----------------
// 256 threads -> 256 samples per block; w staged in smem for frag building
__global__ __launch_bounds__(256) void prep_samp(const float* __restrict__ emp,
                                                 const float* __restrict__ eps,
                                                 const float* __restrict__ rhos,
                                                 const int* __restrict__ idxs) {
    __shared__ float sw[256][16];
    int tid = threadIdx.x;
    int s = blockIdx.x * 256 + tid;

    int idx = idxs[s];
    float rho = rhos[idx];
    float sd = (rho > 20.f) ? rho : log1pf(__expf(rho));
    float wn = 0.f;
#pragma unroll
    for (int d = 0; d < 16; d++) {
        float w = 0.f;
        if (d < D_W) w = fmaf(__ldg(&eps[s * D_W + d]), sd, __ldg(&emp[idx * D_W + d]));
        sw[tid][d] = w;
        g_w16[s * 16 + d] = w;
        wn = fmaf(w, w, wn);
    }
    g_wn[s] = wn;
    __syncthreads();

    // A fragments: 16 row-blocks per block, 32 lanes each = 512 entries
    int rb0 = blockIdx.x * 16;
#pragma unroll
    for (int h = 0; h < 2; h++) {
        int e = h * 256 + tid;             // 0..511
        int rbl = e >> 5;                  // local row-block
        int lane = e & 31, gid = lane >> 2, tg = lane & 3;
        const float* w0 = sw[rbl * 16 + gid];
        const float* w8 = sw[rbl * 16 + gid + 8];
        int k0 = tg * 2;
        uint4 r;
        r.x = packbf(w0[k0], w0[k0 + 1]);
        r.y = packbf(w8[k0], w8[k0 + 1]);
        r.z = packbf(w0[k0 + 8], w0[k0 + 9]);
        r.w = packbf(w8[k0 + 8], w8[k0 + 9]);
        g_Afrag[(rb0 + rbl) * 32 + lane] = r;
    }
}

// ---------------- kernel 3: FUSED regression + tensor-core lse ----------------
// blocks [0, REG_BLOCKS): regression (8 warps, 1 sample/warp, MUFU tanh)
// blocks [REG_BLOCKS, +LSE_BLOCKS): mma + exp2 sum (MUFU ex2)
// Mixing both block types on each SM keeps the MUFU pipe saturated end-to-end.
__global__ __launch_bounds__(256, 4) void fused_main(const float* __restrict__ x,
                                                     const float* __restrict__ y) {
    __shared__ float2 sxy[B_X];

    if (blockIdx.x < REG_BLOCKS) {
        int tid = threadIdx.x;
        for (int i = tid; i < B_X; i += 256)
            sxy[i] = make_float2(x[i], y[i]);
        __syncthreads();

        int wid = tid >> 5, lane = tid & 31;
        int s = blockIdx.x * 8 + wid;

        float wd = (lane < D_W) ? g_w16[s * 16 + lane] : 0.f;
        float p[D_W];
#pragma unroll
        for (int d = 0; d < D_W; d++) p[d] = __shfl_sync(0xffffffffu, wd, d);
        float w10 = p[0], w11 = p[1], b10 = p[2], b11 = p[3];
        float w200 = p[4], w201 = p[5], w210 = p[6], w211 = p[7];
        float b20 = p[8], b21 = p[9], w30 = p[10], w31 = p[11], b3 = p[12];

        float acc = 0.f;
#pragma unroll 8
        for (int t = 0; t < B_X / 32; t++) {
            float2 xy = sxy[t * 32 + lane];
            float h0 = tanh_fast(fmaf(w10, xy.x, b10));
            float h1 = tanh_fast(fmaf(w11, xy.x, b11));
            float z0 = tanh_fast(fmaf(w200, h0, fmaf(w201, h1, b20)));
            float z1 = tanh_fast(fmaf(w210, h0, fmaf(w211, h1, b21)));
            float yp = fmaf(w30, z0, fmaf(w31, z1, b3));
            float d = yp - xy.y;
            acc = fmaf(d, d, acc);
        }
#pragma unroll
        for (int o = 16; o; o >>= 1) acc += __shfl_xor_sync(0xffffffffu, acc, o);
        if (lane == 0) g_dsum[s] = acc;
    } else {
        int bid = blockIdx.x - REG_BLOCKS;      // 0..511
        int wid = threadIdx.x >> 5, lane = threadIdx.x & 31;
        int gid = lane >> 2, tg = lane & 3;
        int chunk = bid >> 6;                   // 0..7
        int grp   = bid & 63;
        int rb = grp * 8 + wid;                 // 0..511
        int s0 = rb * 16;

        uint4 af = g_Afrag[rb * 32 + lane];
        float hw0 = -0.5f * g_wn[s0 + gid];
        float hw8 = -0.5f * g_wn[s0 + gid + 8];
        float S0 = 0.f, S8 = 0.f;

        int nb0 = chunk * NB_PC;
#pragma unroll 4
        for (int i = 0; i < NB_PC; i++) {
            int nb = nb0 + i;
            uint2 bf = g_Bfrag[nb * 32 + lane];
            float4 gu = g_gu[nb * 4 + tg];
            float c0 = hw0, c1 = hw0, c2 = hw8, c3 = hw8;
            asm volatile(
                "mma.sync.aligned.m16n8k16.row.col.f32.bf16.bf16.f32 "
                "{%0,%1,%2,%3}, {%4,%5,%6,%7}, {%8,%9}, {%0,%1,%2,%3};"
                : "+f"(c0), "+f"(c1), "+f"(c2), "+f"(c3)
                : "r"(af.x), "r"(af.y), "r"(af.z), "r"(af.w),
                  "r"(bf.x), "r"(bf.y));
            // t = g*(dot - 0.5||w||^2) + u  (base-2, unshifted; always < 0)
            S0 += exp2_fast(fmaf(gu.x, c0, gu.z));
            S0 += exp2_fast(fmaf(gu.y, c1, gu.w));
            S8 += exp2_fast(fmaf(gu.x, c2, gu.z));
            S8 += exp2_fast(fmaf(gu.y, c3, gu.w));
        }

        S0 += __shfl_xor_sync(0xffffffffu, S0, 1);
        S0 += __shfl_xor_sync(0xffffffffu, S0, 2);
        S8 += __shfl_xor_sync(0xffffffffu, S8, 1);
        S8 += __shfl_xor_sync(0xffffffffu, S8, 2);
        if (tg == 0) {
            g_SP[chunk][s0 + gid]     = S0;
            g_SP[chunk][s0 + gid + 8] = S8;
        }
    }
}

// ---------------- kernel 4: per-block partial reductions ----------------
// 32 blocks x 256 thr; 1 sample/thread; fast log; deterministic block sums.
__global__ __launch_bounds__(256) void reduce_sp() {
    __shared__ double sh[3][8];
    int tid = threadIdx.x;
    int s = blockIdx.x * 256 + tid;

    float S = 0.f;
#pragma unroll
    for (int c = 0; c < NC; c++) S += g_SP[c][s];
    double q  = (double)__logf(S);
    double wn = (double)g_wn[s];
    double ds = (double)g_dsum[s];

    int lane = tid & 31, warp = tid >> 5;
#pragma unroll
    for (int o = 16; o; o >>= 1) {
        q  += __shfl_xor_sync(0xffffffffu, q, o);
        wn += __shfl_xor_sync(0xffffffffu, wn, o);
        ds += __shfl_xor_sync(0xffffffffu, ds, o);
    }
    if (lane == 0) { sh[0][warp] = q; sh[1][warp] = wn; sh[2][warp] = ds; }
    __syncthreads();
    if (warp == 0 && lane < 8) {
        q = sh[0][lane]; wn = sh[1][lane]; ds = sh[2][lane];
#pragma unroll
        for (int o = 4; o; o >>= 1) {
            q  += __shfl_xor_sync(0xffu, q, o);
            wn += __shfl_xor_sync(0xffu, wn, o);
            ds += __shfl_xor_sync(0xffu, ds, o);
        }
        if (lane == 0) {
            g_part[blockIdx.x][0] = q;
            g_part[blockIdx.x][1] = wn;
            g_part[blockIdx.x][2] = ds;
        }
    }
}

// ---------------- kernel 5: final combine (1 warp) ----------------
__global__ void final_kernel(float* __restrict__ out) {
    int lane = threadIdx.x;
    double q = g_part[lane][0], wn = g_part[lane][1], ds = g_part[lane][2];
#pragma unroll
    for (int o = 16; o; o >>= 1) {
        q  += __shfl_xor_sync(0xffffffffu, q, o);
        wn += __shfl_xor_sync(0xffffffffu, wn, o);
        ds += __shfl_xor_sync(0xffffffffu, ds, o);
    }
    if (lane == 0) {
        const double LOG_2PI_D = 1.837877066409345483560659472811;
        double mean_q  = q / (double)N_SAMP - log((double)K_COMP);
        double mean_wn = wn / (double)N_SAMP;
        double mean_d  = ds / (double)N_SAMP;
        double data_lp = -0.5 * 5.0 * mean_d
                       + (double)B_X * 0.5 * (log(5.0) - LOG_2PI_D);
        double prior   = -0.5 * mean_wn - 0.5 * (double)D_W * LOG_2PI_D;
        double kl      = mean_q - prior;
        out[0] = (float)(data_lp - kl);
    }
}

// ---------------- launch ----------------
extern "C" void kernel_launch(void* const* d_in, const int* in_sizes, int n_in,
                              void* d_out, int out_size) {
    const float* emp  = (const float*)d_in[0];
    const float* rhos = (const float*)d_in[1];
    const float* x    = (const float*)d_in[2];
    const float* y    = (const float*)d_in[3];
    const float* eps  = (const float*)d_in[4];
    const int*   idxs = (const int*)d_in[5];
    float* out = (float*)d_out;

    prep_comp<<<(K_COMP + NNB * 32) / 256, 256>>>(emp, rhos);
    prep_samp<<<N_SAMP / 256, 256>>>(emp, eps, rhos, idxs);
    fused_main<<<REG_BLOCKS + LSE_BLOCKS, 256>>>(x, y);
    reduce_sp<<<RED_BLOCKS, 256>>>();
    final_kernel<<<1, 32>>>(out);
}

// round 9
// speedup vs baseline: 3.0438x; 1.0786x over previous
#include <cuda_runtime.h>
#include <math.h>
#include <stdint.h>

#define K_COMP 8192
#define N_SAMP 8192
#define B_X    2048
#define D_W    13

#define LOG_2PI 1.8378770664093453f
#define L2E     1.4426950408889634f

#define NRB   (N_SAMP / 16)     // 512 row-blocks of 16 samples
#define NNB   (K_COMP / 8)      // 1024 col-blocks of 8 components
#define NC    8                 // n-chunks
#define NB_PC (NNB / NC)        // 128 col-blocks per chunk

#define LSE_BLOCKS (NC * 64)            // 512  (first in grid: longest blocks)
#define REG_BLOCKS (N_SAMP / 8)         // 1024 (8 warps/block, 1 sample/warp)
#define RED_BLOCKS 32

// ---------------- scratch (no allocations allowed) ----------------
__device__ float  g_w16[N_SAMP * 16];     // fp32 w, padded k=13..15 = 0
__device__ float  g_wn[N_SAMP];           // ||w||^2 (fp32 exact)
__device__ float4 g_gu[K_COMP / 2];       // (g0,g1,u0,u1) per col-pair
__device__ uint4  g_Afrag[NRB * 32];      // per-lane A fragments (bf16x2 x4)
__device__ uint2  g_Bfrag[NNB * 32];      // per-lane B fragments (bf16x2 x2)
__device__ float  g_dsum[N_SAMP];         // sum_b (y_pred - y)^2
__device__ float  g_SP[NC][N_SAMP];       // per-chunk partial exp-sums
__device__ double g_part[RED_BLOCKS][3];  // per-block (q, wn, dsum) sums
__device__ unsigned g_ticket;             // last-block ticket (self-resetting)

__device__ __forceinline__ float tanh_fast(float x) {
    float r; asm("tanh.approx.f32 %0, %1;" : "=f"(r) : "f"(x)); return r;
}
__device__ __forceinline__ float exp2_fast(float x) {
    float r; asm("ex2.approx.f32 %0, %1;" : "=f"(r) : "f"(x)); return r;
}
// pack two f32 -> bf16x2, lo in low 16 bits
__device__ __forceinline__ unsigned packbf(float lo, float hi) {
    unsigned r; asm("cvt.rn.bf16x2.f32 %0, %1, %2;" : "=r"(r) : "f"(hi), "f"(lo)); return r;
}

// ---------------- kernel 1: ALL prep (block-range split) ----------------
// blocks [0, 32): per-sample w/norm/A-frags     (256 samples per block)
// blocks [32, 32+132): per-component g,u + B-frags (flat index)
__global__ __launch_bounds__(256) void prep_all(const float* __restrict__ emp,
                                                const float* __restrict__ rhos,
                                                const float* __restrict__ eps,
                                                const int* __restrict__ idxs) {
    if (blockIdx.x < 32) {
        __shared__ float sw[256][16];
        int tid = threadIdx.x;
        int s = blockIdx.x * 256 + tid;

        int idx = idxs[s];
        float rho = rhos[idx];
        float sd = (rho > 20.f) ? rho : log1pf(__expf(rho));
        float wn = 0.f;
#pragma unroll
        for (int d = 0; d < 16; d++) {
            float w = 0.f;
            if (d < D_W) w = fmaf(__ldg(&eps[s * D_W + d]), sd, __ldg(&emp[idx * D_W + d]));
            sw[tid][d] = w;
            g_w16[s * 16 + d] = w;
            wn = fmaf(w, w, wn);
        }
        g_wn[s] = wn;
        __syncthreads();

        // A fragments (m16n8k16 row.col A layout), 16 row-blocks per block
        int rb0 = blockIdx.x * 16;
#pragma unroll
        for (int h = 0; h < 2; h++) {
            int e = h * 256 + tid;             // 0..511
            int rbl = e >> 5;
            int lane = e & 31, gid = lane >> 2, tg = lane & 3;
            const float* w0 = sw[rbl * 16 + gid];
            const float* w8 = sw[rbl * 16 + gid + 8];
            int k0 = tg * 2;
            uint4 r;
            r.x = packbf(w0[k0], w0[k0 + 1]);
            r.y = packbf(w8[k0], w8[k0 + 1]);
            r.z = packbf(w0[k0 + 8], w0[k0 + 9]);
            r.w = packbf(w8[k0 + 8], w8[k0 + 9]);
            g_Afrag[(rb0 + rbl) * 32 + lane] = r;
        }
    } else {
        int tid = (blockIdx.x - 32) * 256 + threadIdx.x;
        if (tid < K_COMP) {
            int k = tid;
            float rho = rhos[k];
            float sd = (rho > 20.f) ? rho : log1pf(__expf(rho));   // softplus
            float var = sd * sd;
            float inv = 1.f / var;
            float en = 0.f;
#pragma unroll
            for (int d = 0; d < D_W; d++) {
                float v = __ldg(&emp[k * D_W + d]);
                en = fmaf(v, v, en);
            }
            float c = -0.5f * ((float)D_W * LOG_2PI + (float)D_W * logf(var));
            float g = L2E * inv;
            float u = L2E * (c - 0.5f * inv * en);
            float* gu = (float*)&g_gu[k >> 1];
            gu[(k & 1) + 0] = g;
            gu[(k & 1) + 2] = u;
        } else if (tid < K_COMP + NNB * 32) {
            // B fragments: m16n8k16 row.col B layout (n=gid, k=2tg.. / +8)
            int t2 = tid - K_COMP;
            int lane = t2 & 31, gid = lane >> 2, tg = lane & 3;
            int nb = t2 >> 5;
            int n = nb * 8 + gid;
            int k0 = tg * 2;
            float e0 = __ldg(&emp[n * D_W + k0]);
            float e1 = __ldg(&emp[n * D_W + k0 + 1]);
            float e2 = (k0 + 8 < D_W) ? __ldg(&emp[n * D_W + k0 + 8]) : 0.f;
            float e3 = (k0 + 9 < D_W) ? __ldg(&emp[n * D_W + k0 + 9]) : 0.f;
            uint2 r;
            r.x = packbf(e0, e1);
            r.y = packbf(e2, e3);
            g_Bfrag[t2] = r;
        }
    }
}

// ---------------- kernel 2: FUSED tensor-core lse + regression ----------------
// blocks [0, LSE_BLOCKS): mma + exp2 sum (MUFU ex2) — longer, launched first
// blocks [LSE_BLOCKS, +REG_BLOCKS): regression (MUFU tanh) — shorter, fill tail
__global__ __launch_bounds__(256, 4) void fused_main(const float* __restrict__ x,
                                                     const float* __restrict__ y) {
    __shared__ float2 sxy[B_X];

    if (blockIdx.x < LSE_BLOCKS) {
        int bid = blockIdx.x;                   // 0..511
        int wid = threadIdx.x >> 5, lane = threadIdx.x & 31;
        int gid = lane >> 2, tg = lane & 3;
        int chunk = bid >> 6;                   // 0..7
        int grp   = bid & 63;
        int rb = grp * 8 + wid;                 // 0..511
        int s0 = rb * 16;

        uint4 af = g_Afrag[rb * 32 + lane];
        float hw0 = -0.5f * g_wn[s0 + gid];
        float hw8 = -0.5f * g_wn[s0 + gid + 8];
        float S0 = 0.f, S8 = 0.f;

        int nb0 = chunk * NB_PC;
#pragma unroll 4
        for (int i = 0; i < NB_PC; i++) {
            int nb = nb0 + i;
            uint2 bf = g_Bfrag[nb * 32 + lane];
            float4 gu = g_gu[nb * 4 + tg];
            float c0 = hw0, c1 = hw0, c2 = hw8, c3 = hw8;
            asm volatile(
                "mma.sync.aligned.m16n8k16.row.col.f32.bf16.bf16.f32 "
                "{%0,%1,%2,%3}, {%4,%5,%6,%7}, {%8,%9}, {%0,%1,%2,%3};"
                : "+f"(c0), "+f"(c1), "+f"(c2), "+f"(c3)
                : "r"(af.x), "r"(af.y), "r"(af.z), "r"(af.w),
                  "r"(bf.x), "r"(bf.y));
            // t = g*(dot - 0.5||w||^2) + u  (base-2, unshifted; always < 0)
            S0 += exp2_fast(fmaf(gu.x, c0, gu.z));
            S0 += exp2_fast(fmaf(gu.y, c1, gu.w));
            S8 += exp2_fast(fmaf(gu.x, c2, gu.z));
            S8 += exp2_fast(fmaf(gu.y, c3, gu.w));
        }

        S0 += __shfl_xor_sync(0xffffffffu, S0, 1);
        S0 += __shfl_xor_sync(0xffffffffu, S0, 2);
        S8 += __shfl_xor_sync(0xffffffffu, S8, 1);
        S8 += __shfl_xor_sync(0xffffffffu, S8, 2);
        if (tg == 0) {
            g_SP[chunk][s0 + gid]     = S0;
            g_SP[chunk][s0 + gid + 8] = S8;
        }
    } else {
        int bid = blockIdx.x - LSE_BLOCKS;      // 0..1023
        int tid = threadIdx.x;
        for (int i = tid; i < B_X; i += 256)
            sxy[i] = make_float2(x[i], y[i]);
        __syncthreads();

        int wid = tid >> 5, lane = tid & 31;
        int s = bid * 8 + wid;

        float wd = (lane < D_W) ? g_w16[s * 16 + lane] : 0.f;
        float p[D_W];
#pragma unroll
        for (int d = 0; d < D_W; d++) p[d] = __shfl_sync(0xffffffffu, wd, d);
        float w10 = p[0], w11 = p[1], b10 = p[2], b11 = p[3];
        float w200 = p[4], w201 = p[5], w210 = p[6], w211 = p[7];
        float b20 = p[8], b21 = p[9], w30 = p[10], w31 = p[11], b3 = p[12];

        float acc = 0.f;
#pragma unroll 8
        for (int t = 0; t < B_X / 32; t++) {
            float2 xy = sxy[t * 32 + lane];
            float h0 = tanh_fast(fmaf(w10, xy.x, b10));
            float h1 = tanh_fast(fmaf(w11, xy.x, b11));
            float z0 = tanh_fast(fmaf(w200, h0, fmaf(w201, h1, b20)));
            float z1 = tanh_fast(fmaf(w210, h0, fmaf(w211, h1, b21)));
            float yp = fmaf(w30, z0, fmaf(w31, z1, b3));
            float d = yp - xy.y;
            acc = fmaf(d, d, acc);
        }
#pragma unroll
        for (int o = 16; o; o >>= 1) acc += __shfl_xor_sync(0xffffffffu, acc, o);
        if (lane == 0) g_dsum[s] = acc;
    }
}

// ---------------- kernel 3: reduction + final (last-block pattern) ----------------
// 32 blocks x 256 thr; each block writes deterministic double partials; the
// LAST block to finish sums the 32 partials in fixed index order and emits the
// scalar, then resets the ticket (graph-replay safe).
__global__ __launch_bounds__(256) void reduce_final(float* __restrict__ out) {
    __shared__ double sh[3][8];
    int tid = threadIdx.x;
    int s = blockIdx.x * 256 + tid;

    float S = 0.f;
#pragma unroll
    for (int c = 0; c < NC; c++) S += g_SP[c][s];
    double q  = (double)__logf(S);
    double wn = (double)g_wn[s];
    double ds = (double)g_dsum[s];

    int lane = tid & 31, warp = tid >> 5;
#pragma unroll
    for (int o = 16; o; o >>= 1) {
        q  += __shfl_xor_sync(0xffffffffu, q, o);
        wn += __shfl_xor_sync(0xffffffffu, wn, o);
        ds += __shfl_xor_sync(0xffffffffu, ds, o);
    }
    if (lane == 0) { sh[0][warp] = q; sh[1][warp] = wn; sh[2][warp] = ds; }
    __syncthreads();

    __shared__ int s_last;
    if (tid == 0) {
        double bq = 0.0, bwn = 0.0, bds = 0.0;
#pragma unroll
        for (int i = 0; i < 8; i++) { bq += sh[0][i]; bwn += sh[1][i]; bds += sh[2][i]; }
        g_part[blockIdx.x][0] = bq;
        g_part[blockIdx.x][1] = bwn;
        g_part[blockIdx.x][2] = bds;
        __threadfence();
        unsigned t = atomicAdd(&g_ticket, 1u);
        s_last = (t == RED_BLOCKS - 1) ? 1 : 0;
    }
    __syncthreads();

    if (s_last && tid == 0) {
        double tq = 0.0, twn = 0.0, tds = 0.0;
#pragma unroll
        for (int i = 0; i < RED_BLOCKS; i++) {   // fixed order -> deterministic
            tq  += g_part[i][0];
            twn += g_part[i][1];
            tds += g_part[i][2];
        }
        const double LOG_2PI_D = 1.837877066409345483560659472811;
        double mean_q  = tq / (double)N_SAMP - log((double)K_COMP);
        double mean_wn = twn / (double)N_SAMP;
        double mean_d  = tds / (double)N_SAMP;
        double data_lp = -0.5 * 5.0 * mean_d
                       + (double)B_X * 0.5 * (log(5.0) - LOG_2PI_D);
        double prior   = -0.5 * mean_wn - 0.5 * (double)D_W * LOG_2PI_D;
        double kl      = mean_q - prior;
        out[0] = (float)(data_lp - kl);
        g_ticket = 0;                            // reset for next graph replay
    }
}

// ---------------- launch ----------------
extern "C" void kernel_launch(void* const* d_in, const int* in_sizes, int n_in,
                              void* d_out, int out_size) {
    const float* emp  = (const float*)d_in[0];
    const float* rhos = (const float*)d_in[1];
    const float* x    = (const float*)d_in[2];
    const float* y    = (const float*)d_in[3];
    const float* eps  = (const float*)d_in[4];
    const int*   idxs = (const int*)d_in[5];
    float* out = (float*)d_out;

    prep_all<<<32 + (K_COMP + NNB * 32 + 255) / 256, 256>>>(emp, rhos, eps, idxs);
    fused_main<<<LSE_BLOCKS + REG_BLOCKS, 256>>>(x, y);
    reduce_final<<<RED_BLOCKS, 256>>>(out);
}